// round 9
// baseline (speedup 1.0000x reference)
#include <cuda_runtime.h>
#include <cstdint>

#define N_PULSES 64
#define N_STATES 21
#define THREADS  256
#define WPB      (THREADS / 32)

typedef unsigned long long u64;

// ---- packed f32x2 helpers (FFMA2 in SASS; reachable only via PTX f32x2) ----
__device__ __forceinline__ u64 pk(float lo, float hi) {
    u64 r; asm("mov.b64 %0,{%1,%2};" : "=l"(r) : "f"(lo), "f"(hi)); return r;
}
__device__ __forceinline__ void upk(u64 v, float& lo, float& hi) {
    asm("mov.b64 {%0,%1},%2;" : "=f"(lo), "=f"(hi) : "l"(v));
}
__device__ __forceinline__ u64 fma2(u64 a, u64 b, u64 c) {
    u64 d; asm("fma.rn.f32x2 %0,%1,%2,%3;" : "=l"(d) : "l"(a), "l"(b), "l"(c)); return d;
}
__device__ __forceinline__ u64 mul2(u64 a, u64 b) {
    u64 d; asm("mul.rn.f32x2 %0,%1,%2;" : "=l"(d) : "l"(a), "l"(b)); return d;
}

// TR scalar: int 500 reads small; float 500.0f bit pattern reads huge -> float.
__device__ __forceinline__ float read_scalar(const void* p)
{
    int iv = *(const int*)p;
    if (iv > 0 && iv < 1000000) return (float)iv;
    return *(const float*)p;
}

__global__ __launch_bounds__(THREADS, 1)
void epg_kernel(const float* __restrict__ flip,
                const float* __restrict__ phases,
                const float* __restrict__ T1,
                const float* __restrict__ T2,
                const float* __restrict__ B0,
                const float* __restrict__ B1,
                const void*  __restrict__ TRp,
                float* __restrict__ out,
                int nbatch)
{
    // [0]=cb [1]=c2b [2]=s2b [3]=-sb [4]=-cb [5]=-c2b [6]=-s2b [7]=pad
    __shared__ __align__(16) u64 s_tp[N_PULSES][8];
    // RF-angle table per (t, warp, chain): {sa^2 pair, ca*sa pair}
    __shared__ __align__(16) u64 s_ab[N_PULSES * WPB * 2][2];
    // Per-warp gmem-linear staging (double buffered): 420 floats = 5 comps x 4 batches x 21
    __shared__ __align__(16) float s_stage[2][WPB][420];
    // Dump area for lanes 21..31 (garbage sink, shared across warps)
    __shared__ float s_dump[412];

    const int tid = threadIdx.x;
    if (tid < N_PULSES) {
        float b = phases[tid];
        float sb, cb;
        sincosf(b, &sb, &cb);                 // precise, once per block
        float c2b = cb * cb - sb * sb;
        float s2b = 2.0f * cb * sb;
        s_tp[tid][0] = pk(cb, cb);
        s_tp[tid][1] = pk(c2b, c2b);
        s_tp[tid][2] = pk(s2b, s2b);
        s_tp[tid][3] = pk(-sb, -sb);
        s_tp[tid][4] = pk(-cb, -cb);
        s_tp[tid][5] = pk(-c2b, -c2b);
        s_tp[tid][6] = pk(-s2b, -s2b);
        s_tp[tid][7] = 0ull;
    }
    {   // hoisted per-(t,warp,chain) RF sincos
        const int blockbase = blockIdx.x * (WPB * 4);
        for (int e = tid; e < N_PULSES * WPB * 2; e += THREADS) {
            int t = e >> 4;                   // WPB*2 = 16 entries per t
            int r = e & 15;
            int w = r >> 1;
            int c = r & 1;
            int bb = blockbase + w * 4 + c * 2;
            int i0 = (bb     < nbatch) ? bb     : nbatch - 1;
            int i1 = (bb + 1 < nbatch) ? bb + 1 : nbatch - 1;
            float a = flip[t];
            float sa0, ca0, sa1, ca1;
            __sincosf(a * 0.5f * B1[i0], &sa0, &ca0);
            __sincosf(a * 0.5f * B1[i1], &sa1, &ca1);
            s_ab[e][0] = pk(sa0 * sa0, sa1 * sa1);
            s_ab[e][1] = pk(ca0 * sa0, ca1 * sa1);
        }
    }
    __syncthreads();

    const int lane = tid & 31;
    const int warp = tid >> 5;
    const int base = (blockIdx.x * WPB + warp) * 4;
    if (base >= nbatch) return;

    const int  iA0 = base;
    const int  iA1 = (base + 1 < nbatch) ? base + 1 : base;
    const bool hiA = (base + 1 < nbatch);
    const bool okB = (base + 2 < nbatch);
    const int  iB0 = okB ? base + 2 : base;
    const int  iB1 = (base + 3 < nbatch) ? base + 3 : iB0;
    const bool hiB = (base + 3 < nbatch);
    // Fast (coalesced) path needs 4 valid batches and 16B-aligned comp strides.
    const bool fullwarp = (base + 3 < nbatch) && ((nbatch & 3) == 0);

    const float TR = read_scalar(TRp);
    const float TWO_PI_ML = 2.0f * 3.14159265358979f * 0.001f;

#define MK_CONST(S, i0, i1)                                                    \
    const float E1a##S = expf(-TR / T1[i0]), E1b##S = expf(-TR / T1[i1]);      \
    const float E2a##S = expf(-TR / T2[i0]), E2b##S = expf(-TR / T2[i1]);      \
    float spa##S, cpa##S, spb##S, cpb##S;                                      \
    sincosf(TWO_PI_ML * B0[i0] * TR, &spa##S, &cpa##S);                        \
    sincosf(TWO_PI_ML * B0[i1] * TR, &spb##S, &cpb##S);                        \
    const u64 E1p##S  = pk(E1a##S, E1b##S);                                    \
    const u64 cpr##S  = pk(E2a##S * cpa##S,  E2b##S * cpb##S);                 \
    const u64 cpi##S  = pk(E2a##S * spa##S,  E2b##S * spb##S);                 \
    const u64 cpin##S = pk(-E2a##S * spa##S, -E2b##S * spb##S);                \
    const u64 zadd##S = (lane == 0) ? pk(1.0f - E1a##S, 1.0f - E1b##S) : 0ull;

    MK_CONST(A, iA0, iA1)
    MK_CONST(B, iB0, iB1)
#undef MK_CONST

    const u64 m1p  = pk(-1.0f, -1.0f);
    const u64 m2p  = pk(-2.0f, -2.0f);
    const u64 onep = pk(1.0f, 1.0f);

    u64 FprA = 0ull, FpiA = 0ull, FmrA = 0ull, FmiA = 0ull;
    u64 FprB = 0ull, FpiB = 0ull, FmrB = 0ull, FmiB = 0ull;
    u64 ZA = (lane == 0) ? pk(1.0f, 1.0f) : 0ull;
    u64 ZB = ZA;

    const size_t cs = (size_t)nbatch * N_STATES;            // component stride
    float* oA = out + (size_t)iA0 * N_STATES + lane;        // scalar-fallback base
    const bool active = (lane < N_STATES);
    const bool edgeFp = (lane == 0 || lane >= N_STATES);
    const bool edgeFm = (lane >= N_STATES - 1);

    // ---- coalesced-copy precompute (loop-invariant) ----
    // warp stage = 420 floats, gmem-linear: f = comp*84 + b*21 + s.
    // 105 float4; float4 j -> comp = j/21, float-offset = 4*(j%21).
    const int j1 = lane + 32, j2 = lane + 64;
    const int j3 = (lane + 96 < 105) ? lane + 96 : 104;   // clamped for safe LDS
    float* gp0; float* gp1; float* gp2; float* gp3;
    {
        float* gb = out + (size_t)base * N_STATES;
        int c0 = lane / 21, p0 = lane - 21 * c0;
        int c1 = j1 / 21,   p1 = j1 - 21 * c1;
        int c2 = j2 / 21,   p2 = j2 - 21 * c2;
        int c3 = j3 / 21,   p3 = j3 - 21 * c3;
        gp0 = gb + (size_t)c0 * cs + 4 * p0;
        gp1 = gb + (size_t)c1 * cs + 4 * p1;
        gp2 = gb + (size_t)c2 * cs + 4 * p2;
        gp3 = gb + (size_t)c3 * cs + 4 * p3;
    }
    float* const sts0 = (lane < N_STATES) ? &s_stage[0][warp][lane]
                                          : &s_dump[lane - N_STATES];
    float* const sts1 = (lane < N_STATES) ? &s_stage[1][warp][lane]
                                          : &s_dump[lane - N_STATES];
    const float4* const ldb0 = (const float4*)&s_stage[0][warp][0];
    const float4* const ldb1 = (const float4*)&s_stage[1][warp][0];

    size_t toff = 0;                                        // t * 5 * cs

#define ADVANCE(S, ABIDX, Fpn, Fpi_n, Fmn, Fmi_n, Zn)                          \
    u64 Fpn, Fpi_n, Fmn, Fmi_n, Zn;                                            \
    {                                                                          \
        const ulonglong2 sc =                                                  \
            *(const ulonglong2*)&s_ab[(t * WPB + warp) * 2 + (ABIDX)][0];      \
        const u64 sa2p = sc.x, casap = sc.y;                                   \
        const u64 zr  = fma2(E1p##S, Z##S, zadd##S);                           \
        const u64 npr = fma2(cpr##S, Fpr##S, mul2(cpin##S, Fpi##S));           \
        const u64 npi = fma2(cpr##S, Fpi##S, mul2(cpi##S,  Fpr##S));           \
        const u64 nmr = fma2(cpr##S, Fmr##S, mul2(cpi##S,  Fmi##S));           \
        const u64 nmi = fma2(cpr##S, Fmi##S, mul2(cpin##S, Fmr##S));           \
        const u64 ca2p = fma2(sa2p, m1p, onep);                                \
        const u64 k7   = fma2(sa2p, m2p, onep);                                \
        const u64 k1  = mul2(sa2p, tp1);                                       \
        const u64 k2  = mul2(sa2p, tp2);                                       \
        const u64 k1n = mul2(sa2p, tp5);                                       \
        const u64 k2n = mul2(sa2p, tp6);                                       \
        const u64 k3n = mul2(casap, tp3);                                      \
        const u64 k4  = mul2(casap, tp0);                                      \
        const u64 k4n = mul2(casap, tp4);                                      \
        Fpn   = fma2(k3n, zr, fma2(k2,  nmi, fma2(k1,  nmr, mul2(ca2p, npr))));\
        Fpi_n = fma2(k4,  zr, fma2(k1n, nmi, fma2(k2,  nmr, mul2(ca2p, npi))));\
        Fmn   = fma2(k3n, zr, fma2(ca2p, nmr, fma2(k2n, npi, mul2(k1, npr)))); \
        Fmi_n = fma2(k4n, zr, fma2(ca2p, nmi, fma2(k1n, npi, mul2(k2n, npr))));\
        Zn    = fma2(k7,  zr, fma2(k3n, nmr, fma2(k3n, npr,                    \
                                  fma2(k4n, nmi, mul2(k4, npi)))));            \
    }

#define STEP(T, STSB, LDB)                                                     \
    {                                                                          \
        const int t = (T);                                                     \
        const ulonglong2* tpv = (const ulonglong2*)&s_tp[t][0];                \
        const ulonglong2 tq0 = tpv[0], tq1 = tpv[1], tq2 = tpv[2];             \
        const u64 tp6v = s_tp[t][6];                                           \
        const u64 tp0 = tq0.x, tp1 = tq0.y, tp2 = tq1.x, tp3 = tq1.y;          \
        const u64 tp4 = tq2.x, tp5 = tq2.y, tp6 = tp6v;                        \
        ADVANCE(A, 0, FpnA, FpinA, FmnA, FminA, ZnA)                           \
        u64 sFprA = __shfl_up_sync(0xffffffffu, FpnA, 1);                      \
        u64 sFpiA = __shfl_up_sync(0xffffffffu, FpinA, 1);                     \
        u64 sFmrA = __shfl_down_sync(0xffffffffu, FmnA, 1);                    \
        u64 sFmiA = __shfl_down_sync(0xffffffffu, FminA, 1);                   \
        ADVANCE(B, 1, FpnB, FpinB, FmnB, FminB, ZnB)                           \
        u64 sFprB = __shfl_up_sync(0xffffffffu, FpnB, 1);                      \
        u64 sFpiB = __shfl_up_sync(0xffffffffu, FpinB, 1);                     \
        u64 sFmrB = __shfl_down_sync(0xffffffffu, FmnB, 1);                    \
        u64 sFmiB = __shfl_down_sync(0xffffffffu, FminB, 1);                   \
        if (edgeFp) { sFprA = 0ull; sFpiA = 0ull; sFprB = 0ull; sFpiB = 0ull; }\
        if (edgeFm) { sFmrA = 0ull; sFmiA = 0ull; sFmrB = 0ull; sFmiB = 0ull; }\
        FprA = sFprA; FpiA = sFpiA; FmrA = sFmrA; FmiA = sFmiA; ZA = ZnA;      \
        FprB = sFprB; FpiB = sFpiB; FmrB = sFmrB; FmiB = sFmiB; ZB = ZnB;      \
        if (fullwarp) {                                                        \
            float l, h;                                                        \
            upk(FprA, l, h); STSB[0]        = l; STSB[21]       = h;           \
            upk(FpiA, l, h); STSB[84]       = l; STSB[105]      = h;           \
            upk(FmrA, l, h); STSB[168]      = l; STSB[189]      = h;           \
            upk(FmiA, l, h); STSB[252]      = l; STSB[273]      = h;           \
            upk(ZA,   l, h); STSB[336]      = l; STSB[357]      = h;           \
            upk(FprB, l, h); STSB[42]       = l; STSB[63]       = h;           \
            upk(FpiB, l, h); STSB[126]      = l; STSB[147]      = h;           \
            upk(FmrB, l, h); STSB[210]      = l; STSB[231]      = h;           \
            upk(FmiB, l, h); STSB[294]      = l; STSB[315]      = h;           \
            upk(ZB,   l, h); STSB[378]      = l; STSB[399]      = h;           \
            __syncwarp();                                                      \
            float4 v0 = LDB[lane];                                             \
            float4 v1 = LDB[j1];                                               \
            float4 v2 = LDB[j2];                                               \
            float4 v3 = LDB[j3];                                               \
            *(float4*)(gp0 + toff) = v0;                                       \
            *(float4*)(gp1 + toff) = v1;                                       \
            *(float4*)(gp2 + toff) = v2;                                       \
            if (lane < 9) *(float4*)(gp3 + toff) = v3;                         \
        } else if (active) {                                                   \
            float l0,h0,l1,h1,l2,h2,l3,h3,l4,h4;                               \
            upk(FprA,l0,h0); upk(FpiA,l1,h1); upk(FmrA,l2,h2);                 \
            upk(FmiA,l3,h3); upk(ZA, l4,h4);                                   \
            float* otp = oA + toff;                                            \
            otp[0] = l0; otp[cs] = l1; otp[2*cs] = l2;                         \
            otp[3*cs] = l3; otp[4*cs] = l4;                                    \
            if (hiA) {                                                         \
                otp[N_STATES] = h0; otp[N_STATES+cs] = h1;                     \
                otp[N_STATES+2*cs] = h2; otp[N_STATES+3*cs] = h3;              \
                otp[N_STATES+4*cs] = h4;                                       \
            }                                                                  \
            if (okB) {                                                         \
                upk(FprB,l0,h0); upk(FpiB,l1,h1); upk(FmrB,l2,h2);             \
                upk(FmiB,l3,h3); upk(ZB, l4,h4);                               \
                otp[2*N_STATES] = l0; otp[2*N_STATES+cs] = l1;                 \
                otp[2*N_STATES+2*cs] = l2; otp[2*N_STATES+3*cs] = l3;          \
                otp[2*N_STATES+4*cs] = l4;                                     \
                if (hiB) {                                                     \
                    otp[3*N_STATES] = h0; otp[3*N_STATES+cs] = h1;             \
                    otp[3*N_STATES+2*cs] = h2; otp[3*N_STATES+3*cs] = h3;      \
                    otp[3*N_STATES+4*cs] = h4;                                 \
                }                                                              \
            }                                                                  \
        }                                                                      \
        toff += 5u * cs;                                                       \
    }

#pragma unroll 1
    for (int tt = 0; tt < N_PULSES; tt += 2) {
        STEP(tt,     sts0, ldb0)
        STEP(tt + 1, sts1, ldb1)
    }
#undef ADVANCE
#undef STEP
}

extern "C" void kernel_launch(void* const* d_in, const int* in_sizes, int n_in,
                              void* d_out, int out_size)
{
    const float* flip   = (const float*)d_in[0];
    const float* phases = (const float*)d_in[1];
    const float* T1     = (const float*)d_in[2];
    const float* T2     = (const float*)d_in[3];
    const float* B0     = (const float*)d_in[4];
    const float* B1     = (const float*)d_in[5];
    const void*  TRp    = d_in[6];

    const int nbatch = in_sizes[2];          // T1 element count = batch
    float* out = (float*)d_out;
    const int nwarps = (nbatch + 3) / 4;     // 4 batches per warp (2 chains)
    const int blocks = (nwarps + WPB - 1) / WPB;
    epg_kernel<<<blocks, THREADS>>>(flip, phases, T1, T2, B0, B1, TRp, out, nbatch);
}

// round 10
// speedup vs baseline: 1.3591x; 1.3591x over previous
#include <cuda_runtime.h>
#include <cstdint>

#define N_PULSES 64
#define N_STATES 21
#define THREADS  256
#define WARPS_PER_BLOCK (THREADS / 32)

typedef unsigned long long u64;

// ---- packed f32x2 helpers (FFMA2 in SASS; reachable only via PTX f32x2) ----
__device__ __forceinline__ u64 pk(float lo, float hi) {
    u64 r; asm("mov.b64 %0,{%1,%2};" : "=l"(r) : "f"(lo), "f"(hi)); return r;
}
__device__ __forceinline__ void upk(u64 v, float& lo, float& hi) {
    asm("mov.b64 {%0,%1},%2;" : "=f"(lo), "=f"(hi) : "l"(v));
}
__device__ __forceinline__ u64 fma2(u64 a, u64 b, u64 c) {
    u64 d; asm("fma.rn.f32x2 %0,%1,%2,%3;" : "=l"(d) : "l"(a), "l"(b), "l"(c)); return d;
}
__device__ __forceinline__ u64 mul2(u64 a, u64 b) {
    u64 d; asm("mul.rn.f32x2 %0,%1,%2;" : "=l"(d) : "l"(a), "l"(b)); return d;
}

// TR scalar: int 500 reads small; float 500.0f bit pattern reads huge -> float.
__device__ __forceinline__ float read_scalar(const void* p)
{
    int iv = *(const int*)p;
    if (iv > 0 && iv < 1000000) return (float)iv;
    return *(const float*)p;
}

__global__ __launch_bounds__(THREADS, 1)
void epg_kernel(const float* __restrict__ flip,
                const float* __restrict__ phases,
                const float* __restrict__ T1,
                const float* __restrict__ T2,
                const float* __restrict__ B0,
                const float* __restrict__ B1,
                const void*  __restrict__ TRp,
                float* __restrict__ out,
                int nbatch)
{
    // Broadcast-packed trig table (batch-independent, shared by both chains):
    // [0]=cb, [1]=c2b, [2]=s2b, [3]=-sb, [4]=-cb, [5]=-c2b, [6]=-s2b, [7]=flip
    __shared__ u64 s_tp[N_PULSES][8];

    const int tid = threadIdx.x;
    if (tid < N_PULSES) {
        float b = phases[tid];
        float sb, cb;
        sincosf(b, &sb, &cb);                 // precise, once per block
        float c2b = cb * cb - sb * sb;
        float s2b = 2.0f * cb * sb;
        s_tp[tid][0] = pk(cb, cb);
        s_tp[tid][1] = pk(c2b, c2b);
        s_tp[tid][2] = pk(s2b, s2b);
        s_tp[tid][3] = pk(-sb, -sb);
        s_tp[tid][4] = pk(-cb, -cb);
        s_tp[tid][5] = pk(-c2b, -c2b);
        s_tp[tid][6] = pk(-s2b, -s2b);
        float a = flip[tid];
        s_tp[tid][7] = pk(a, a);
    }
    __syncthreads();

    const int lane = tid & 31;
    const int warp = tid >> 5;
    const int base = (blockIdx.x * WARPS_PER_BLOCK + warp) * 4;
    if (base >= nbatch) return;

    // Chain A: batches base, base+1.  Chain B: batches base+2, base+3.
    const int  iA0 = base;
    const int  iA1 = (base + 1 < nbatch) ? base + 1 : base;
    const bool hiA = (base + 1 < nbatch);
    const bool okB = (base + 2 < nbatch);
    const int  iB0 = okB ? base + 2 : base;
    const int  iB1 = (base + 3 < nbatch) ? base + 3 : iB0;
    const bool hiB = (base + 3 < nbatch);

    const float TR = read_scalar(TRp);
    const float TWO_PI_ML = 2.0f * 3.14159265358979f * 0.001f;

#define MK_CONST(S, i0, i1)                                                    \
    const float E1a##S = expf(-TR / T1[i0]), E1b##S = expf(-TR / T1[i1]);      \
    const float E2a##S = expf(-TR / T2[i0]), E2b##S = expf(-TR / T2[i1]);      \
    float spa##S, cpa##S, spb##S, cpb##S;                                      \
    sincosf(TWO_PI_ML * B0[i0] * TR, &spa##S, &cpa##S);                        \
    sincosf(TWO_PI_ML * B0[i1] * TR, &spb##S, &cpb##S);                        \
    const u64 E1p##S  = pk(E1a##S, E1b##S);                                    \
    const u64 cpr##S  = pk(E2a##S * cpa##S,  E2b##S * cpb##S);                 \
    const u64 cpi##S  = pk(E2a##S * spa##S,  E2b##S * spb##S);                 \
    const u64 cpin##S = pk(-E2a##S * spa##S, -E2b##S * spb##S);                \
    const u64 zadd##S = (lane == 0) ? pk(1.0f - E1a##S, 1.0f - E1b##S) : 0ull; \
    const float b1h0##S = 0.5f * B1[i0], b1h1##S = 0.5f * B1[i1];

    MK_CONST(A, iA0, iA1)
    MK_CONST(B, iB0, iB1)
#undef MK_CONST

    const u64 m2p  = pk(-2.0f, -2.0f);
    const u64 onep = pk(1.0f, 1.0f);

    // Packed state (lane = EPG order; lanes >= 21 stay exactly zero)
    u64 FprA = 0ull, FpiA = 0ull, FmrA = 0ull, FmiA = 0ull;
    u64 FprB = 0ull, FpiB = 0ull, FmrB = 0ull, FmiB = 0ull;
    u64 ZA = (lane == 0) ? pk(1.0f, 1.0f) : 0ull;
    u64 ZB = ZA;

    const size_t cs = (size_t)nbatch * N_STATES;            // component stride
    float* oA = out + (size_t)iA0 * N_STATES + lane;        // [t][c][batch][state]
    const bool active = (lane < N_STATES);
    const bool edgeFp = (lane == 0 || lane >= N_STATES);
    const bool edgeFm = (lane >= N_STATES - 1);

#define ADVANCE(S, Fpn, Fpi_n, Fmn, Fmi_n, Zn)                                 \
    u64 Fpn, Fpi_n, Fmn, Fmi_n, Zn;                                            \
    {                                                                          \
        const u64 zr  = fma2(E1p##S, Z##S, zadd##S);                           \
        const u64 npr = fma2(cpr##S, Fpr##S, mul2(cpin##S, Fpi##S));           \
        const u64 npi = fma2(cpr##S, Fpi##S, mul2(cpi##S,  Fpr##S));           \
        const u64 nmr = fma2(cpr##S, Fmr##S, mul2(cpi##S,  Fmi##S));           \
        const u64 nmi = fma2(cpr##S, Fmi##S, mul2(cpin##S, Fmr##S));           \
        float sa0, ca0, sa1, ca1;                                              \
        __sincosf(aflip * b1h0##S, &sa0, &ca0);                                \
        __sincosf(aflip * b1h1##S, &sa1, &ca1);                                \
        const u64 sap   = pk(sa0, sa1);                                        \
        const u64 cap   = pk(ca0, ca1);                                        \
        const u64 ca2p  = mul2(cap, cap);                                      \
        const u64 sa2p  = mul2(sap, sap);                                      \
        const u64 casap = mul2(cap, sap);                                      \
        const u64 k1  = mul2(sa2p, tp1);                                       \
        const u64 k2  = mul2(sa2p, tp2);                                       \
        const u64 k1n = mul2(sa2p, tp5);                                       \
        const u64 k2n = mul2(sa2p, tp6);                                       \
        const u64 k3n = mul2(casap, tp3);                                      \
        const u64 k4  = mul2(casap, tp0);                                      \
        const u64 k4n = mul2(casap, tp4);                                      \
        const u64 k7  = fma2(sa2p, m2p, onep);                                 \
        Fpn   = fma2(k3n, zr, fma2(k2,  nmi, fma2(k1,  nmr, mul2(ca2p, npr))));\
        Fpi_n = fma2(k4,  zr, fma2(k1n, nmi, fma2(k2,  nmr, mul2(ca2p, npi))));\
        Fmn   = fma2(k3n, zr, fma2(ca2p, nmr, fma2(k2n, npi, mul2(k1, npr)))); \
        Fmi_n = fma2(k4n, zr, fma2(ca2p, nmi, fma2(k1n, npi, mul2(k2n, npr))));\
        Zn    = fma2(k7,  zr, fma2(k3n, nmr, fma2(k3n, npr,                    \
                                  fma2(k4n, nmi, mul2(k4, npi)))));            \
    }

    // Streaming (evict-first) stores: output is written once, never re-read.
#define STORE5(ptr, v0, v1, v2, v3, v4, off, half)                             \
    {                                                                          \
        float l0,h0,l1,h1,l2,h2,l3,h3,l4,h4;                                   \
        upk(v0,l0,h0); upk(v1,l1,h1); upk(v2,l2,h2);                           \
        upk(v3,l3,h3); upk(v4,l4,h4);                                          \
        __stcs((ptr) + (off),          l0);                                    \
        __stcs((ptr) + (off) + cs,     l1);                                    \
        __stcs((ptr) + (off) + 2*cs,   l2);                                    \
        __stcs((ptr) + (off) + 3*cs,   l3);                                    \
        __stcs((ptr) + (off) + 4*cs,   l4);                                    \
        if (half) {                                                            \
            __stcs((ptr) + (off) + N_STATES,        h0);                       \
            __stcs((ptr) + (off) + N_STATES + cs,   h1);                       \
            __stcs((ptr) + (off) + N_STATES + 2*cs, h2);                       \
            __stcs((ptr) + (off) + N_STATES + 3*cs, h3);                       \
            __stcs((ptr) + (off) + N_STATES + 4*cs, h4);                       \
        }                                                                      \
    }

#pragma unroll 1
    for (int t = 0; t < N_PULSES; ++t) {
        const u64* tp = s_tp[t];
        const u64 tp0 = tp[0], tp1 = tp[1], tp2 = tp[2], tp3 = tp[3];
        const u64 tp4 = tp[4], tp5 = tp[5], tp6 = tp[6];
        float aflip, dummy;
        upk(tp[7], aflip, dummy);

        // --- chain A compute, then launch its shuffles ---
        ADVANCE(A, FpnA, FpinA, FmnA, FminA, ZnA)
        u64 sFprA = __shfl_up_sync(0xffffffffu, FpnA, 1);
        u64 sFpiA = __shfl_up_sync(0xffffffffu, FpinA, 1);
        u64 sFmrA = __shfl_down_sync(0xffffffffu, FmnA, 1);
        u64 sFmiA = __shfl_down_sync(0xffffffffu, FminA, 1);

        // --- chain B compute fills chain A's shuffle latency ---
        ADVANCE(B, FpnB, FpinB, FmnB, FminB, ZnB)
        u64 sFprB = __shfl_up_sync(0xffffffffu, FpnB, 1);
        u64 sFpiB = __shfl_up_sync(0xffffffffu, FpinB, 1);
        u64 sFmrB = __shfl_down_sync(0xffffffffu, FmnB, 1);
        u64 sFmiB = __shfl_down_sync(0xffffffffu, FminB, 1);

        if (edgeFp) { sFprA = 0ull; sFpiA = 0ull; sFprB = 0ull; sFpiB = 0ull; }
        if (edgeFm) { sFmrA = 0ull; sFmiA = 0ull; sFmrB = 0ull; sFmiB = 0ull; }
        FprA = sFprA; FpiA = sFpiA; FmrA = sFmrA; FmiA = sFmiA; ZA = ZnA;
        FprB = sFprB; FpiB = sFpiB; FmrB = sFmrB; FmiB = sFmiB; ZB = ZnB;

        if (active) {
            float* ot = oA + (size_t)t * 5u * cs;
            STORE5(ot, FprA, FpiA, FmrA, FmiA, ZnA, 0, hiA)
            if (okB)
                STORE5(ot, FprB, FpiB, FmrB, FmiB, ZnB, 2 * N_STATES, hiB)
        }
    }
#undef ADVANCE
#undef STORE5
}

extern "C" void kernel_launch(void* const* d_in, const int* in_sizes, int n_in,
                              void* d_out, int out_size)
{
    const float* flip   = (const float*)d_in[0];
    const float* phases = (const float*)d_in[1];
    const float* T1     = (const float*)d_in[2];
    const float* T2     = (const float*)d_in[3];
    const float* B0     = (const float*)d_in[4];
    const float* B1     = (const float*)d_in[5];
    const void*  TRp    = d_in[6];

    const int nbatch = in_sizes[2];          // T1 element count = batch
    float* out = (float*)d_out;
    const int nwarps = (nbatch + 3) / 4;     // 4 batches per warp (2 chains)
    const int blocks = (nwarps + WARPS_PER_BLOCK - 1) / WARPS_PER_BLOCK;
    epg_kernel<<<blocks, THREADS>>>(flip, phases, T1, T2, B0, B1, TRp, out, nbatch);
}